// round 5
// baseline (speedup 1.0000x reference)
#include <cuda_runtime.h>

#define W    30
#define TT   4096
#define FF   128
#define F2   (FF / 2)          // 64 float2 per row
#define NS   (TT - W + 1)      // 4067 window starts
#define SEG  180               // per CTA (two halves of 90)
#define HALF 90                // 3 * 30 per y-slice
#define NG   (HALF / W)        // 3
#define EPSF 1e-4f

__global__ __launch_bounds__(128)
void ts_zscore_kernel(const float2* __restrict__ x, float2* __restrict__ out)
{
    const int f2   = threadIdx.x;        // feature pair 0..63
    const int half = threadIdx.y;        // 0..1: sub-segment within the CTA
    const int b    = blockIdx.x;

    int k0 = blockIdx.y * SEG;
    if (k0 > NS - SEG) k0 = NS - SEG;    // clamp: tail block overlaps (same values)
    k0 += half * HALF;

    const float2* __restrict__ xp = x   + ((size_t)b * TT + k0) * F2 + f2;
    float2*       __restrict__ op = out + ((size_t)b * NS + k0) * F2 + f2;

    float sx = 0.f, sy = 0.f, s2x = 0.f, s2y = 0.f;

    // Prime with the first 29 rows. For half==1 these rows were already
    // fetched by half==0 in the same CTA -> L1/L2 hit or L2 miss-merge.
#pragma unroll
    for (int i = 0; i < W - 1; ++i) {
        const float2 v = __ldg(xp + (size_t)i * F2);
        sx += v.x;  sy += v.y;
        s2x = fmaf(v.x, v.x, s2x);
        s2y = fmaf(v.y, v.y, s2y);
    }

#pragma unroll 1
    for (int g = 0; g < NG; ++g) {
#pragma unroll
        for (int u = 0; u < W; ++u) {
            // New row entering the window for output u
            const float2 nv = __ldg(xp + (size_t)(u + W - 1) * F2);

            const float ssx  = sx + nv.x;
            const float ssy  = sy + nv.y;
            const float ss2x = fmaf(nv.x, nv.x, s2x);
            const float ss2y = fmaf(nv.y, nv.y, s2y);

            const float mx = ssx * (1.0f / W);
            const float my = ssy * (1.0f / W);
            const float qx = ss2x * (1.0f / W);
            const float qy = ss2y * (1.0f / W);

            float vx = fmaxf(fmaf(-mx, mx, qx), 0.0f);
            float vy = fmaxf(fmaf(-my, my, qy), 0.0f);

            float sdx, sdy;
            asm("sqrt.approx.f32 %0, %1;" : "=f"(sdx) : "f"(vx));
            asm("sqrt.approx.f32 %0, %1;" : "=f"(sdy) : "f"(vy));

            float2 r;
            r.x = __fdividef(nv.x - mx, sdx + EPSF);
            r.y = __fdividef(nv.y - my, sdy + EPSF);
            __stcs(op + (size_t)u * F2, r);      // streaming store (write-once)

            // Row leaving the window: re-load (L1/L2 hit, loaded 29 iters ago)
            const float2 ov = __ldg(xp + (size_t)u * F2);
            sx  = ssx  - ov.x;
            sy  = ssy  - ov.y;
            s2x = fmaf(-ov.x, ov.x, ss2x);
            s2y = fmaf(-ov.y, ov.y, ss2y);
        }
        xp += (size_t)W * F2;
        op += (size_t)W * F2;
    }
}

extern "C" void kernel_launch(void* const* d_in, const int* in_sizes, int n_in,
                              void* d_out, int out_size)
{
    (void)n_in; (void)out_size;
    const float2* x = (const float2*)d_in[0];
    float2* out = (float2*)d_out;

    const int B = in_sizes[0] / (TT * FF);       // 64 for this problem
    dim3 block(F2, 2);                            // 128 threads
    dim3 grid(B, (NS + SEG - 1) / SEG);           // (64, 23)
    ts_zscore_kernel<<<grid, block>>>(x, out);
}

// round 6
// speedup vs baseline: 1.0782x; 1.0782x over previous
#include <cuda_runtime.h>

#define W    30
#define TT   4096
#define FF   128
#define NS   (TT - W + 1)      // 4067 window starts
#define SEG  150               // 5 * 30 — grid (64,28)=1792 CTAs, single wave
#define NGROUPS (SEG / W)      // 5
#define PF   6                 // prefetch depth (divides 30 -> static ring indices)
#define EPSF 1e-4f

__global__ __launch_bounds__(FF)
void ts_zscore_kernel(const float* __restrict__ x, float* __restrict__ out)
{
    const int f = threadIdx.x;          // feature column
    const int b = blockIdx.x;           // batch
    int k0 = blockIdx.y * SEG;          // first window start for this block
    if (k0 > NS - SEG) k0 = NS - SEG;   // clamp: tail block overlaps prior (same values)

    const float* __restrict__ xp = x   + ((size_t)b * TT + k0) * FF + f;
    float*       __restrict__ op = out + ((size_t)b * NS + k0) * FF + f;

    float s = 0.0f, s2 = 0.0f;

    // Prime sums with rows 0..28 (relative to k0).
#pragma unroll
    for (int i = 0; i < W - 1; ++i) {
        const float val = __ldg(xp + (size_t)i * FF);
        s += val;
        s2 = fmaf(val, val, s2);
    }

    // Prefetch FIFO: nvb[i] holds the nv row for upcoming iteration i.
    // Fill with rows 29..34 (always in bounds: k0 <= 3917 -> row <= 3951).
    float nvb[PF];
#pragma unroll
    for (int i = 0; i < PF; ++i)
        nvb[i] = __ldg(xp + (size_t)(W - 1 + i) * FF);

    // Rows remaining in the tensor past the current xp row (for prefetch clamp).
    int rows_left = TT - 1 - k0;

#pragma unroll 1
    for (int g = 0; g < NGROUPS; ++g) {
#pragma unroll
        for (int u = 0; u < W; ++u) {
            // nv for this iteration was prefetched PF iterations ago.
            const float nv = nvb[u % PF];

            // Prefetch nv for iteration u+PF: row (u + PF + W - 1) relative
            // to current xp. Clamp to the last valid row; clamped (garbage)
            // values map to iterations >= SEG and are never consumed.
            {
                const int r = u + PF + (W - 1);
                const int r_eff = (r < rows_left) ? r : rows_left;
                nvb[u % PF] = __ldg(xp + (size_t)r_eff * FF);
            }

            const float ss  = s + nv;           // window sum
            const float ss2 = fmaf(nv, nv, s2);

            const float mean   = ss  * (1.0f / W);
            const float meansq = ss2 * (1.0f / W);
            float var = fmaf(-mean, mean, meansq);
            var = fmaxf(var, 0.0f);

            float stdv;
            asm("sqrt.approx.f32 %0, %1;" : "=f"(stdv) : "f"(var));
            const float r = __fdividef(nv - mean, stdv + EPSF);

            __stcs(op + (size_t)u * FF, r);     // streaming store (write-once)

            // Row leaving the window: re-load (this thread loaded it 29
            // iterations ago -> L1/L2 hit, no DRAM traffic).
            const float ov = __ldg(xp + (size_t)u * FF);
            s  = ss  - ov;
            s2 = fmaf(-ov, ov, ss2);
        }
        xp += (size_t)W * FF;
        op += (size_t)W * FF;
        rows_left -= W;
    }
}

extern "C" void kernel_launch(void* const* d_in, const int* in_sizes, int n_in,
                              void* d_out, int out_size)
{
    (void)n_in; (void)out_size;
    const float* x = (const float*)d_in[0];
    float* out = (float*)d_out;

    const int B = in_sizes[0] / (TT * FF);   // 64 for this problem
    dim3 grid(B, (NS + SEG - 1) / SEG);      // (64, 28)
    ts_zscore_kernel<<<grid, FF>>>(x, out);
}

// round 7
// speedup vs baseline: 1.1050x; 1.0249x over previous
#include <cuda_runtime.h>

#define W    30
#define TT   4096
#define FF   128
#define NS   (TT - W + 1)      // 4067 window starts
#define SEG  150               // 5 * 30 — grid (64,28)=1792 CTAs
#define NGROUPS (SEG / W)      // 5
#define SB   6                 // nv-load batch size
#define NSB  (W / SB)          // 5 sub-blocks per group
#define EPSF 1e-4f

__global__ __launch_bounds__(FF, 12)
void ts_zscore_kernel(const float* __restrict__ x, float* __restrict__ out)
{
    const int f = threadIdx.x;          // feature column
    const int b = blockIdx.x;           // batch
    int k0 = blockIdx.y * SEG;          // first window start for this block
    if (k0 > NS - SEG) k0 = NS - SEG;   // clamp: tail block overlaps prior (same values)

    const float* __restrict__ xp = x   + ((size_t)b * TT + k0) * FF + f;
    float*       __restrict__ op = out + ((size_t)b * NS + k0) * FF + f;

    float s = 0.0f, s2 = 0.0f;

    // Prime sums with rows 0..28 (relative to k0).
#pragma unroll
    for (int i = 0; i < W - 1; ++i) {
        const float val = __ldg(xp + (size_t)i * FF);
        s += val;
        s2 = fmaf(val, val, s2);
    }

    // nv batch for the first sub-block: rows 29..34 (always in bounds).
    float nvb[SB];
#pragma unroll
    for (int u = 0; u < SB; ++u)
        nvb[u] = __ldg(xp + (size_t)(W - 1 + u) * FF);

#pragma unroll 1
    for (int g = 0; g < NGROUPS; ++g) {
#pragma unroll
        for (int sb = 0; sb < NSB; ++sb) {
            // Prefetch the NEXT batch of 6 nv rows (static offsets, no clamp).
            // Rows (sb+1)*6 + 29 + u relative to xp — in bounds for every
            // batch except the one past the final sub-block of the final
            // group, which is skipped (one predicate per group, not per elem).
            float nvc[SB];
            if ((sb < NSB - 1) || (g < NGROUPS - 1)) {
#pragma unroll
                for (int u = 0; u < SB; ++u)
                    nvc[u] = __ldg(xp + (size_t)((sb + 1) * SB + (W - 1) + u) * FF);
            } else {
#pragma unroll
                for (int u = 0; u < SB; ++u)
                    nvc[u] = 0.0f;  // never consumed
            }

#pragma unroll
            for (int u = 0; u < SB; ++u) {
                const int lt = sb * SB + u;        // local output index 0..29
                const float nv = nvb[u];

                const float ss  = s + nv;          // window sum
                const float ss2 = fmaf(nv, nv, s2);

                const float mean   = ss  * (1.0f / W);
                const float meansq = ss2 * (1.0f / W);
                float var = fmaxf(fmaf(-mean, mean, meansq), 0.0f);

                float stdv;
                asm("sqrt.approx.f32 %0, %1;" : "=f"(stdv) : "f"(var));
                const float r = __fdividef(nv - mean, stdv + EPSF);

                __stcs(op + (size_t)lt * FF, r);   // streaming store (write-once)

                // Row leaving the window: re-load (loaded by this thread 29
                // iterations ago -> L1/L2 hit, no DRAM traffic).
                const float ov = __ldg(xp + (size_t)lt * FF);
                s  = ss  - ov;
                s2 = fmaf(-ov, ov, ss2);
            }

            // Rotate double buffer (register MOVs, static).
#pragma unroll
            for (int u = 0; u < SB; ++u)
                nvb[u] = nvc[u];
        }
        xp += (size_t)W * FF;
        op += (size_t)W * FF;
    }
}

extern "C" void kernel_launch(void* const* d_in, const int* in_sizes, int n_in,
                              void* d_out, int out_size)
{
    (void)n_in; (void)out_size;
    const float* x = (const float*)d_in[0];
    float* out = (float*)d_out;

    const int B = in_sizes[0] / (TT * FF);   // 64 for this problem
    dim3 grid(B, (NS + SEG - 1) / SEG);      // (64, 28)
    ts_zscore_kernel<<<grid, FF>>>(x, out);
}

// round 8
// speedup vs baseline: 1.3443x; 1.2165x over previous
#include <cuda_runtime.h>
#include <cstdint>

#define W      30
#define TT     4096
#define FF     128
#define NS     (TT - W + 1)        // 4067 window starts
#define SEG    150                 // outputs per CTA (5 groups of 30)
#define NG     5
#define CH     30                  // rows per chunk == W (static smem offsets)
#define NCHUNK 6                   // 180 staged rows >= 179 needed
#define CHF    (CH * FF)           // floats per chunk = 3840
#define SMEM_BYTES (NCHUNK * CHF * 4)   // 92160
#define EPSF   1e-4f

__device__ __forceinline__ void cp16(uint32_t saddr, const void* gaddr) {
    asm volatile("cp.async.cg.shared.global [%0], [%1], 16;" :: "r"(saddr), "l"(gaddr));
}
__device__ __forceinline__ void cp_commit() {
    asm volatile("cp.async.commit_group;");
}
template <int N>
__device__ __forceinline__ void cp_wait() {
    asm volatile("cp.async.wait_group %0;" :: "n"(N));
}

// One group of 30 outputs. sg = chunk g base (+f), sg1 = chunk g+1 base (+f),
// op = output row base (+f). Returns updated (s, s2).
__device__ __noinline__ float2 group30(const float* __restrict__ sg,
                                       const float* __restrict__ sg1,
                                       float* __restrict__ op,
                                       float s, float s2)
{
#pragma unroll
    for (int u = 0; u < W; ++u) {
        // nv row (local) = u + 29: chunk g offset 29 for u==0, else chunk g+1 offset u-1
        const float nv = (u == 0) ? sg[29 * FF] : sg1[(u - 1) * FF];

        const float ss  = s + nv;
        const float ss2 = fmaf(nv, nv, s2);

        const float mean   = ss  * (1.0f / W);
        const float meansq = ss2 * (1.0f / W);
        float var = fmaxf(fmaf(-mean, mean, meansq), 0.0f);

        float stdv;
        asm("sqrt.approx.f32 %0, %1;" : "=f"(stdv) : "f"(var));
        const float r = __fdividef(nv - mean, stdv + EPSF);

        __stcs(op + (size_t)u * FF, r);

        const float ov = sg[u * FF];       // row leaving the window (smem)
        s  = ss  - ov;
        s2 = fmaf(-ov, ov, ss2);
    }
    return make_float2(s, s2);
}

__global__ __launch_bounds__(FF)
void ts_zscore_kernel(const float* __restrict__ x, float* __restrict__ out)
{
    extern __shared__ float sm[];
    const int f = threadIdx.x;
    const int b = blockIdx.x;
    int k0 = blockIdx.y * SEG;
    if (k0 > NS - SEG) k0 = NS - SEG;     // tail block overlaps prior (same values)

    const uint32_t sbase = (uint32_t)__cvta_generic_to_shared(sm);
    const float* __restrict__ xb = x + (size_t)b * TT * FF;

    // Issue ALL 6 chunk copies up front (92 KB in flight per CTA).
    // Chunk c = rows k0+c*30 .. k0+c*30+29 (512 B/row). 960 16-byte units
    // per chunk, strided across 128 threads (7 full + 1 predicated round).
#pragma unroll
    for (int c = 0; c < NCHUNK; ++c) {
#pragma unroll
        for (int i = 0; i < 8; ++i) {
            const int idx = threadIdx.x + i * FF;       // 16B-unit index
            if (i < 7 || idx < CH * 32) {               // 960 units per chunk
                int grow = k0 + c * CH + (idx >> 5);    // global row
                if (grow > TT - 1) grow = TT - 1;       // clamp: row never consumed
                const float* g = xb + (size_t)grow * FF + ((idx & 31) << 2);
                cp16(sbase + (uint32_t)((c * CHF + idx * 4) * 4), g);
            }
        }
        cp_commit();
    }

    float* __restrict__ op = out + ((size_t)b * NS + k0) * FF + f;

    // Prime s,s2 with local rows 0..28 (chunk 0).
    cp_wait<5>(); __syncthreads();
    float s = 0.0f, s2 = 0.0f;
#pragma unroll
    for (int i = 0; i < W - 1; ++i) {
        const float v = sm[i * FF + f];
        s += v;
        s2 = fmaf(v, v, s2);
    }

    float2 st = make_float2(s, s2);
    cp_wait<4>(); __syncthreads();
    st = group30(sm + 0 * CHF + f, sm + 1 * CHF + f, op + (size_t)0 * W * FF, st.x, st.y);
    cp_wait<3>(); __syncthreads();
    st = group30(sm + 1 * CHF + f, sm + 2 * CHF + f, op + (size_t)1 * W * FF, st.x, st.y);
    cp_wait<2>(); __syncthreads();
    st = group30(sm + 2 * CHF + f, sm + 3 * CHF + f, op + (size_t)2 * W * FF, st.x, st.y);
    cp_wait<1>(); __syncthreads();
    st = group30(sm + 3 * CHF + f, sm + 4 * CHF + f, op + (size_t)3 * W * FF, st.x, st.y);
    cp_wait<0>(); __syncthreads();
    st = group30(sm + 4 * CHF + f, sm + 5 * CHF + f, op + (size_t)4 * W * FF, st.x, st.y);
}

extern "C" void kernel_launch(void* const* d_in, const int* in_sizes, int n_in,
                              void* d_out, int out_size)
{
    (void)n_in; (void)out_size;
    const float* x = (const float*)d_in[0];
    float* out = (float*)d_out;

    cudaFuncSetAttribute(ts_zscore_kernel,
                         cudaFuncAttributeMaxDynamicSharedMemorySize, SMEM_BYTES);

    const int B = in_sizes[0] / (TT * FF);   // 64 for this problem
    dim3 grid(B, (NS + SEG - 1) / SEG);      // (64, 28)
    ts_zscore_kernel<<<grid, FF, SMEM_BYTES>>>(x, out);
}